// round 8
// baseline (speedup 1.0000x reference)
#include <cuda_runtime.h>
#include <cuda_bf16.h>
#include <cstdint>

// AdaBoost fused classifier via legacy mma.sync TF32 (base-ISA sm_103).
//   logits[N,E] = x[N,F] @ W[E,F]^T + b
//   pred = (logit > 0); acc = sum_e pred*trunc(alpha); out = sign(acc)
// |logit| < TAU rescued by warp-cooperative exact fp32 recompute.
//
// BM=128 x BN=256(=E) x BK=32, 256 thr, warp grid 2(m) x 4(n), warp tile
// 64x64 (m16n8k8.tf32, mt=4 x nt=8). Intra-chunk fragment double-buffer,
// 3-stage cp.async pipeline for B (pre-converted tf32 in __device__ scratch),
// A via LDG->cvt->STS ping-pong.

#define F_DIM 512
#define E_DIM 256
#define BM 128
#define BK 32
#define NCHUNK (F_DIM / BK)
#define TAU 4e-3f
#define QCAP 2048

#define SA 36
#define A_WORDS (BM * SA)              // 4608 per buffer
#define B_WORDS (E_DIM * SA)           // 9216 per buffer
#define DSMEM_BYTES ((2 * A_WORDS + 3 * B_WORDS) * 4)   // 147456

__device__ uint32_t g_Wtf32[E_DIM * F_DIM];

static __device__ __forceinline__ uint32_t to_tf32(float x) {
    uint32_t r;
    asm("cvt.rna.tf32.f32 %0, %1;" : "=r"(r) : "f"(x));
    return r;
}
static __device__ __forceinline__ uint32_t smem_u32(const void* p) {
    uint32_t a;
    asm("{ .reg .u64 t; cvta.to.shared.u64 t, %1; cvt.u32.u64 %0, t; }"
        : "=r"(a) : "l"(p));
    return a;
}

#define CP_ASYNC16(dst, src) \
    asm volatile("cp.async.ca.shared.global [%0], [%1], 16;" \
                 :: "r"(dst), "l"(src) : "memory")
#define CP_COMMIT() asm volatile("cp.async.commit_group;" ::: "memory")
#define CP_WAIT1() asm volatile("cp.async.wait_group 1;" ::: "memory")

#define MMA_TF32(c, a, b)                                                  \
    asm volatile(                                                          \
        "mma.sync.aligned.m16n8k8.row.col.f32.tf32.tf32.f32 "              \
        "{%0,%1,%2,%3}, {%4,%5,%6,%7}, {%8,%9}, {%0,%1,%2,%3};"            \
        : "+f"((c)[0]), "+f"((c)[1]), "+f"((c)[2]), "+f"((c)[3])           \
        : "r"((a)[0]), "r"((a)[1]), "r"((a)[2]), "r"((a)[3]),              \
          "r"((b)[0]), "r"((b)[1]))

__global__ void prep_kernel(const float* __restrict__ Wm) {
    int i = (blockIdx.x * blockDim.x + threadIdx.x) * 4;
    float4 v = *reinterpret_cast<const float4*>(Wm + i);
    uint4 o;
    o.x = to_tf32(v.x); o.y = to_tf32(v.y);
    o.z = to_tf32(v.z); o.w = to_tf32(v.w);
    *reinterpret_cast<uint4*>(g_Wtf32 + i) = o;
}

__global__ __launch_bounds__(256, 1)
void adaboost_mma_kernel(const float* __restrict__ x,
                         const float* __restrict__ Wm,
                         const float* __restrict__ bvec,
                         const float* __restrict__ alphas,
                         float* __restrict__ out) {
    extern __shared__ uint32_t sm[];
    uint32_t* As = sm;                       // [2][128][SA]
    uint32_t* Bs = sm + 2 * A_WORDS;         // [3][256][SA]

    __shared__ float s_b[E_DIM];
    __shared__ float s_ta[E_DIM];
    __shared__ float psum[BM][4];
    __shared__ float s_rsum[BM];
    __shared__ int s_nresc;
    __shared__ uint32_t s_q[QCAP];

    const int tid  = threadIdx.x;
    const int wid  = tid >> 5;
    const int lane = tid & 31;
    const int g    = lane >> 2;
    const int tg   = lane & 3;
    const int wm   = wid & 1;      // 2 warp-rows (64 rows each)
    const int wn   = wid >> 1;     // 4 warp-cols (64 cols each)
    const int m0   = blockIdx.x * BM;

    s_b[tid]  = bvec[tid];
    s_ta[tid] = truncf(alphas[tid]);
    if (tid < BM) s_rsum[tid] = 0.0f;
    if (tid == 0) s_nresc = 0;

    const uint32_t Bs_u = smem_u32(Bs);

    float acc[4][8][4];
#pragma unroll
    for (int i = 0; i < 4; i++)
#pragma unroll
        for (int j = 0; j < 8; j++)
#pragma unroll
            for (int r = 0; r < 4; r++) acc[i][j][r] = 0.0f;

    // A mapping: 4 float4 per thread, row = tid/2, q = (tid&1)*4 + h
    const int a_row = tid >> 1;
    const int a_q0  = (tid & 1) * 4;

    // ---- prologue ----
    {
        // B0, B1 via cp.async (groups 0 and 1)
#pragma unroll
        for (int l = 0; l < 8; l++) {
            int idx = tid + 256 * l;
            int n = idx >> 3, q = idx & 7;
            CP_ASYNC16(Bs_u + (n * SA + q * 4) * 4,
                       (const char*)(g_Wtf32 + (size_t)n * F_DIM + q * 4));
        }
        CP_COMMIT();
#pragma unroll
        for (int l = 0; l < 8; l++) {
            int idx = tid + 256 * l;
            int n = idx >> 3, q = idx & 7;
            CP_ASYNC16(Bs_u + (B_WORDS + n * SA + q * 4) * 4,
                       (const char*)(g_Wtf32 + (size_t)n * F_DIM + BK + q * 4));
        }
        CP_COMMIT();
        // A0: LDG -> cvt -> STS
#pragma unroll
        for (int h = 0; h < 4; h++) {
            float4 v = *reinterpret_cast<const float4*>(
                x + (size_t)(m0 + a_row) * F_DIM + (a_q0 + h) * 4);
            uint4 o;
            o.x = to_tf32(v.x); o.y = to_tf32(v.y);
            o.z = to_tf32(v.z); o.w = to_tf32(v.w);
            *reinterpret_cast<uint4*>(&As[a_row * SA + (a_q0 + h) * 4]) = o;
        }
    }

    // ---- main loop ----
    for (int t = 0; t < NCHUNK; t++) {
        const int pa2 = t & 1;          // A buffer
        const int pb3 = t % 3;          // B buffer
        CP_WAIT1();                      // B(t) landed (B(t+1) may be in flight)
        __syncthreads();

        // issue B(t+2) into buffer (t+2)%3 ; always commit to keep group count
        if (t + 2 < NCHUNK) {
            const int kn = (t + 2) * BK;
            const int nb = (t + 2) % 3;
#pragma unroll
            for (int l = 0; l < 8; l++) {
                int idx = tid + 256 * l;
                int n = idx >> 3, q = idx & 7;
                CP_ASYNC16(Bs_u + (nb * B_WORDS + n * SA + q * 4) * 4,
                           (const char*)(g_Wtf32 + (size_t)n * F_DIM + kn + q * 4));
            }
        }
        CP_COMMIT();

        // A(t+1) -> regs (consumed after compute)
        float4 pa[4];
        if (t + 1 < NCHUNK) {
            const int kn = (t + 1) * BK;
#pragma unroll
            for (int h = 0; h < 4; h++)
                pa[h] = *reinterpret_cast<const float4*>(
                    x + (size_t)(m0 + a_row) * F_DIM + kn + (a_q0 + h) * 4);
        }

        // ---- compute with fragment double-buffer ----
        const uint32_t* Ap = As + pa2 * A_WORDS;
        const uint32_t* Bp = Bs + pb3 * B_WORDS;

        uint32_t afr[2][4][4], bfr[2][8][2];
        // load ks=0 fragments
        {
            const int kc = tg;
#pragma unroll
            for (int mt = 0; mt < 4; mt++) {
                int rb = wm * 64 + mt * 16;
                afr[0][mt][0] = Ap[(rb + g)     * SA + kc];
                afr[0][mt][1] = Ap[(rb + g + 8) * SA + kc];
                afr[0][mt][2] = Ap[(rb + g)     * SA + kc + 4];
                afr[0][mt][3] = Ap[(rb + g + 8) * SA + kc + 4];
            }
#pragma unroll
            for (int nt = 0; nt < 8; nt++) {
                int n = wn * 64 + nt * 8 + g;
                bfr[0][nt][0] = Bp[n * SA + kc];
                bfr[0][nt][1] = Bp[n * SA + kc + 4];
            }
        }
#pragma unroll
        for (int ks = 0; ks < 4; ks++) {
            const int cur = ks & 1, nxt = cur ^ 1;
            if (ks < 3) {
                const int kc = (ks + 1) * 8 + tg;
#pragma unroll
                for (int mt = 0; mt < 4; mt++) {
                    int rb = wm * 64 + mt * 16;
                    afr[nxt][mt][0] = Ap[(rb + g)     * SA + kc];
                    afr[nxt][mt][1] = Ap[(rb + g + 8) * SA + kc];
                    afr[nxt][mt][2] = Ap[(rb + g)     * SA + kc + 4];
                    afr[nxt][mt][3] = Ap[(rb + g + 8) * SA + kc + 4];
                }
#pragma unroll
                for (int nt = 0; nt < 8; nt++) {
                    int n = wn * 64 + nt * 8 + g;
                    bfr[nxt][nt][0] = Bp[n * SA + kc];
                    bfr[nxt][nt][1] = Bp[n * SA + kc + 4];
                }
            }
#pragma unroll
            for (int mt = 0; mt < 4; mt++)
#pragma unroll
                for (int nt = 0; nt < 8; nt++)
                    MMA_TF32(acc[mt][nt], afr[cur][mt], bfr[cur][nt]);
        }

        // ---- commit A(t+1) ----
        if (t + 1 < NCHUNK) {
            uint32_t* An = As + (pa2 ^ 1) * A_WORDS;
#pragma unroll
            for (int h = 0; h < 4; h++) {
                uint4 o;
                o.x = to_tf32(pa[h].x); o.y = to_tf32(pa[h].y);
                o.z = to_tf32(pa[h].z); o.w = to_tf32(pa[h].w);
                *reinterpret_cast<uint4*>(&An[a_row * SA + (a_q0 + h) * 4]) = o;
            }
        }
    }

    // ---------------- epilogue ----------------
#pragma unroll
    for (int mt = 0; mt < 4; mt++) {
#pragma unroll
        for (int half = 0; half < 2; half++) {
            int rowl = wm * 64 + mt * 16 + g + half * 8;
            float s = 0.0f;
#pragma unroll
            for (int nt = 0; nt < 8; nt++) {
#pragma unroll
                for (int j = 0; j < 2; j++) {
                    int col = wn * 64 + nt * 8 + 2 * tg + j;
                    float logit = acc[mt][nt][half * 2 + j] + s_b[col];
                    if (fabsf(logit) < TAU) {
                        int qi = atomicAdd(&s_nresc, 1);
                        if (qi < QCAP) {
                            s_q[qi] = ((uint32_t)rowl << 8) | (uint32_t)col;
                        } else {
                            const float* xr = x + (size_t)(m0 + rowl) * F_DIM;
                            const float* wr = Wm + (size_t)col * F_DIM;
                            float a = 0.0f;
                            for (int f = 0; f < F_DIM; f++)
                                a = fmaf(__ldg(xr + f), __ldg(wr + f), a);
                            if (a + s_b[col] > 0.0f) s += s_ta[col];
                        }
                    } else if (logit > 0.0f) {
                        s += s_ta[col];
                    }
                }
            }
            s += __shfl_xor_sync(0xffffffffu, s, 1);
            s += __shfl_xor_sync(0xffffffffu, s, 2);
            if (tg == 0) psum[rowl][wn] = s;
        }
    }
    __syncthreads();

    // ---- warp-cooperative rescue ----
    {
        const int nresc = min(s_nresc, QCAP);
        for (int i = wid; i < nresc; i += 8) {
            uint32_t ent = s_q[i];
            int rowl = (int)(ent >> 8);
            int col  = (int)(ent & 0xFF);
            const float* xr = x + (size_t)(m0 + rowl) * F_DIM;
            const float* wr = Wm + (size_t)col * F_DIM;
            float a0 = 0.0f, a1 = 0.0f;
#pragma unroll
            for (int j = 0; j < 16; j += 2) {
                a0 = fmaf(__ldg(xr + j * 32 + lane), __ldg(wr + j * 32 + lane), a0);
                a1 = fmaf(__ldg(xr + (j + 1) * 32 + lane), __ldg(wr + (j + 1) * 32 + lane), a1);
            }
            float a = a0 + a1;
#pragma unroll
            for (int o = 16; o > 0; o >>= 1)
                a += __shfl_xor_sync(0xffffffffu, a, o);
            if (lane == 0 && a + s_b[col] > 0.0f)
                atomicAdd(&s_rsum[rowl], s_ta[col]);
        }
    }
    __syncthreads();

    if (tid < BM) {
        float s = psum[tid][0] + psum[tid][1] + psum[tid][2] + psum[tid][3]
                + s_rsum[tid];
        out[m0 + tid] = (s > 0.0f) ? 1.0f : ((s < 0.0f) ? -1.0f : 0.0f);
    }
}

extern "C" void kernel_launch(void* const* d_in, const int* in_sizes, int n_in,
                              void* d_out, int out_size) {
    const float* x      = (const float*)d_in[0];   // [N, F]
    const float* Wm     = (const float*)d_in[1];   // [E, F]
    const float* bvec   = (const float*)d_in[2];   // [E]
    const float* alphas = (const float*)d_in[3];   // [E]
    float* out = (float*)d_out;                    // [N]

    const int E = in_sizes[2];         // 256
    const int F = in_sizes[1] / E;     // 512
    const int N = in_sizes[0] / F;     // 131072

    (void)E; (void)F;
    prep_kernel<<<(E_DIM * F_DIM) / (256 * 4), 256>>>(Wm);

    cudaFuncSetAttribute(adaboost_mma_kernel,
                         cudaFuncAttributeMaxDynamicSharedMemorySize, DSMEM_BYTES);
    adaboost_mma_kernel<<<N / BM, 256, DSMEM_BYTES>>>(x, Wm, bvec, alphas, out);
}

// round 9
// speedup vs baseline: 1.4744x; 1.4744x over previous
#include <cuda_runtime.h>
#include <cuda_bf16.h>
#include <cstdint>

// AdaBoost fused classifier via legacy mma.sync TF32 (base-ISA sm_103).
//   logits[N,E] = x[N,F] @ W[E,F]^T + b
//   pred = (logit > 0); acc = sum_e pred*trunc(alpha); out = sign(acc)
// |logit| < TAU rescued by warp-cooperative exact fp32 recompute.
//
// R7 structure (BM=64, 256 thr, 2 CTAs/SM, warp tile 32x64) with
// FRAGMENT-ORDER smem layouts:
//   - W pre-converted to tf32 in MMA-fragment order -> cp.async streams it,
//     B fragment = one LDS.64 per (nt), conflict-free.
//   - A committed to smem in fragment order -> A fragment = one LDS.128.
// Mainloop LDS issues per warp-chunk: 96 -> 40.

#define F_DIM 512
#define E_DIM 256
#define BM 64
#define BK 32
#define NCHUNK (F_DIM / BK)   // 16
#define TAU 4e-3f
#define QCAP 512

#define AREG 132                     // words per A fragment region (128 + 4 pad)
#define A_WORDS (16 * AREG)          // 2112 words per buffer
#define B_WORDS 8192                 // words per buffer (256n x 32k)
#define DSMEM_BYTES ((2 * A_WORDS + 2 * B_WORDS) * 4)   // 82432

// W in tf32, fragment order: [t][wn][ks][nt][lane][w]
//   word = t*8192 + (wn*4+ks)*512 + nt*64 + (g*4+tg)*2 + w
__device__ uint32_t g_Wfrag[E_DIM * F_DIM];

static __device__ __forceinline__ uint32_t to_tf32(float x) {
    uint32_t r;
    asm("cvt.rna.tf32.f32 %0, %1;" : "=r"(r) : "f"(x));
    return r;
}
static __device__ __forceinline__ uint32_t smem_u32(const void* p) {
    uint32_t a;
    asm("{ .reg .u64 t; cvta.to.shared.u64 t, %1; cvt.u32.u64 %0, t; }"
        : "=r"(a) : "l"(p));
    return a;
}

#define CP_ASYNC16(dst, src) \
    asm volatile("cp.async.ca.shared.global [%0], [%1], 16;" \
                 :: "r"(dst), "l"(src) : "memory")
#define CP_COMMIT() asm volatile("cp.async.commit_group;" ::: "memory")
#define CP_WAIT_ALL() asm volatile("cp.async.wait_group 0;" ::: "memory")

#define MMA_TF32(c, a, b)                                                  \
    asm volatile(                                                          \
        "mma.sync.aligned.m16n8k8.row.col.f32.tf32.tf32.f32 "              \
        "{%0,%1,%2,%3}, {%4,%5,%6,%7}, {%8,%9}, {%0,%1,%2,%3};"            \
        : "+f"((c)[0]), "+f"((c)[1]), "+f"((c)[2]), "+f"((c)[3])           \
        : "r"((a)[0]), "r"((a)[1]), "r"((a)[2]), "r"((a)[3]),              \
          "r"((b)[0]), "r"((b)[1]))

// ---- prep: convert W to tf32 AND permute into fragment order ----
__global__ void prep_kernel(const float* __restrict__ Wm) {
    int idx = blockIdx.x * blockDim.x + threadIdx.x;   // (n, k4)
    int n  = idx >> 7;
    int k4 = idx & 127;
    float4 v = *reinterpret_cast<const float4*>(Wm + (size_t)n * F_DIM + k4 * 4);
    uint32_t c0 = to_tf32(v.x), c1 = to_tf32(v.y);
    uint32_t c2 = to_tf32(v.z), c3 = to_tf32(v.w);

    int k0 = k4 * 4;
    int t  = k0 >> 5;
    int ks = (k0 >> 3) & 3;
    int w  = (k0 & 7) >> 2;          // khi: constant over the 4 elems
    int wn = n >> 6, nt = (n >> 3) & 7, g = n & 7;
    uint32_t base = (uint32_t)t * 8192 + (wn * 4 + ks) * 512 + nt * 64 + g * 8 + w;
    g_Wfrag[base + 0] = c0;          // tg = 0..3 stride 2
    g_Wfrag[base + 2] = c1;
    g_Wfrag[base + 4] = c2;
    g_Wfrag[base + 6] = c3;
}

__global__ __launch_bounds__(256, 2)
void adaboost_mma_kernel(const float* __restrict__ x,
                         const float* __restrict__ Wm,
                         const float* __restrict__ bvec,
                         const float* __restrict__ alphas,
                         float* __restrict__ out) {
    extern __shared__ uint32_t sm[];
    uint32_t* As = sm;                       // [2][16 regions][AREG]
    uint32_t* Bs = sm + 2 * A_WORDS;         // [2][8192] fragment order

    __shared__ float s_b[E_DIM];
    __shared__ float s_ta[E_DIM];
    __shared__ float psum[BM][4];
    __shared__ float s_rsum[BM];
    __shared__ int s_nresc;
    __shared__ uint32_t s_q[QCAP];

    const int tid  = threadIdx.x;
    const int wid  = tid >> 5;
    const int lane = tid & 31;
    const int g    = lane >> 2;
    const int tg   = lane & 3;
    const int wm   = wid & 1;      // 2 warp-rows (32 rows each)
    const int wn   = wid >> 1;     // 4 warp-cols (64 cols each)
    const int m0   = blockIdx.x * BM;

    s_b[tid]  = bvec[tid];
    s_ta[tid] = truncf(alphas[tid]);
    if (tid < BM) s_rsum[tid] = 0.0f;
    if (tid == 0) s_nresc = 0;

    const uint32_t Bs_u = smem_u32(Bs);

    float acc[2][8][4];
#pragma unroll
    for (int i = 0; i < 2; i++)
#pragma unroll
        for (int j = 0; j < 8; j++)
#pragma unroll
            for (int r = 0; r < 4; r++) acc[i][j][r] = 0.0f;

    // A commit mapping: thread handles row a_row, k-group a_ks (8 consecutive k)
    const int a_row = tid >> 2;          // 0..63
    const int a_ks  = tid & 3;           // ks of this thread's k-octet
    const int a_rt  = a_row >> 4;        // region row-tile 0..3
    const int a_g   = a_row & 7;
    const int a_h   = (a_row >> 3) & 1;  // word parity (row vs row+8)
    const uint32_t a_base = (uint32_t)(a_rt * 4 + a_ks) * AREG + a_g * 16 + a_h;

    // ---- prologue: chunk 0 ----
#pragma unroll
    for (int l = 0; l < 8; l++) {
        int u = tid + 256 * l;
        CP_ASYNC16(Bs_u + u * 16, (const char*)(g_Wfrag + u * 4));
    }
    CP_COMMIT();
    {
#pragma unroll
        for (int hv = 0; hv < 2; hv++) {
            float4 v = *reinterpret_cast<const float4*>(
                x + (size_t)(m0 + a_row) * F_DIM + a_ks * 8 + hv * 4);
            uint32_t* dst = As + a_base + 2 * hv;
            dst[0]  = to_tf32(v.x);
            dst[4]  = to_tf32(v.y);
            dst[8]  = to_tf32(v.z);
            dst[12] = to_tf32(v.w);
        }
    }

    // ---- main loop ----
    for (int t = 0; t < NCHUNK; t++) {
        const int p = t & 1;
        CP_WAIT_ALL();
        __syncthreads();

        // issue B(t+1)
        if (t + 1 < NCHUNK) {
#pragma unroll
            for (int l = 0; l < 8; l++) {
                int u = tid + 256 * l;
                CP_ASYNC16(Bs_u + ((p ^ 1) * B_WORDS) * 4 + u * 16,
                           (const char*)(g_Wfrag + (t + 1) * B_WORDS + u * 4));
            }
        }
        CP_COMMIT();

        // A(t+1) -> regs
        float4 pa[2];
        if (t + 1 < NCHUNK) {
            const int kn = (t + 1) * BK;
#pragma unroll
            for (int hv = 0; hv < 2; hv++)
                pa[hv] = *reinterpret_cast<const float4*>(
                    x + (size_t)(m0 + a_row) * F_DIM + kn + a_ks * 8 + hv * 4);
        }

        // ---- compute on buffer p ----
        const uint32_t* Ap = As + p * A_WORDS;
        const uint32_t* Bp = Bs + p * B_WORDS;
#pragma unroll
        for (int ks = 0; ks < 4; ks++) {
            uint32_t afr[2][4];
#pragma unroll
            for (int mt = 0; mt < 2; mt++) {
                uint4 q = *reinterpret_cast<const uint4*>(
                    Ap + ((wm * 2 + mt) * 4 + ks) * AREG + lane * 4);
                afr[mt][0] = q.x; afr[mt][1] = q.y;
                afr[mt][2] = q.z; afr[mt][3] = q.w;
            }
            uint32_t bfr[8][2];
#pragma unroll
            for (int nt = 0; nt < 8; nt++) {
                uint2 q = *reinterpret_cast<const uint2*>(
                    Bp + (wn * 4 + ks) * 512 + nt * 64 + lane * 2);
                bfr[nt][0] = q.x; bfr[nt][1] = q.y;
            }
#pragma unroll
            for (int mt = 0; mt < 2; mt++)
#pragma unroll
                for (int nt = 0; nt < 8; nt++)
                    MMA_TF32(acc[mt][nt], afr[mt], bfr[nt]);
        }

        // ---- commit A(t+1) in fragment order ----
        if (t + 1 < NCHUNK) {
            uint32_t* An = As + (p ^ 1) * A_WORDS;
#pragma unroll
            for (int hv = 0; hv < 2; hv++) {
                uint32_t* dst = An + a_base + 2 * hv;
                dst[0]  = to_tf32(pa[hv].x);
                dst[4]  = to_tf32(pa[hv].y);
                dst[8]  = to_tf32(pa[hv].z);
                dst[12] = to_tf32(pa[hv].w);
            }
        }
    }

    // ---------------- epilogue ----------------
#pragma unroll
    for (int mt = 0; mt < 2; mt++) {
#pragma unroll
        for (int half = 0; half < 2; half++) {
            int rowl = wm * 32 + mt * 16 + g + half * 8;
            float s = 0.0f;
#pragma unroll
            for (int nt = 0; nt < 8; nt++) {
#pragma unroll
                for (int j = 0; j < 2; j++) {
                    int col = wn * 64 + nt * 8 + 2 * tg + j;
                    float logit = acc[mt][nt][half * 2 + j] + s_b[col];
                    if (fabsf(logit) < TAU) {
                        int qi = atomicAdd(&s_nresc, 1);
                        if (qi < QCAP) {
                            s_q[qi] = ((uint32_t)rowl << 8) | (uint32_t)col;
                        } else {
                            const float* xr = x + (size_t)(m0 + rowl) * F_DIM;
                            const float* wr = Wm + (size_t)col * F_DIM;
                            float a = 0.0f;
                            for (int f = 0; f < F_DIM; f++)
                                a = fmaf(__ldg(xr + f), __ldg(wr + f), a);
                            if (a + s_b[col] > 0.0f) s += s_ta[col];
                        }
                    } else if (logit > 0.0f) {
                        s += s_ta[col];
                    }
                }
            }
            s += __shfl_xor_sync(0xffffffffu, s, 1);
            s += __shfl_xor_sync(0xffffffffu, s, 2);
            if (tg == 0) psum[rowl][wn] = s;
        }
    }
    __syncthreads();

    // ---- warp-cooperative rescue ----
    {
        const int nresc = min(s_nresc, QCAP);
        for (int i = wid; i < nresc; i += 8) {
            uint32_t ent = s_q[i];
            int rowl = (int)(ent >> 8);
            int col  = (int)(ent & 0xFF);
            const float* xr = x + (size_t)(m0 + rowl) * F_DIM;
            const float* wr = Wm + (size_t)col * F_DIM;
            float a0 = 0.0f, a1 = 0.0f;
#pragma unroll
            for (int j = 0; j < 16; j += 2) {
                a0 = fmaf(__ldg(xr + j * 32 + lane), __ldg(wr + j * 32 + lane), a0);
                a1 = fmaf(__ldg(xr + (j + 1) * 32 + lane), __ldg(wr + (j + 1) * 32 + lane), a1);
            }
            float a = a0 + a1;
#pragma unroll
            for (int o = 16; o > 0; o >>= 1)
                a += __shfl_xor_sync(0xffffffffu, a, o);
            if (lane == 0 && a + s_b[col] > 0.0f)
                atomicAdd(&s_rsum[rowl], s_ta[col]);
        }
    }
    __syncthreads();

    if (tid < BM) {
        float s = psum[tid][0] + psum[tid][1] + psum[tid][2] + psum[tid][3]
                + s_rsum[tid];
        out[m0 + tid] = (s > 0.0f) ? 1.0f : ((s < 0.0f) ? -1.0f : 0.0f);
    }
}

extern "C" void kernel_launch(void* const* d_in, const int* in_sizes, int n_in,
                              void* d_out, int out_size) {
    const float* x      = (const float*)d_in[0];   // [N, F]
    const float* Wm     = (const float*)d_in[1];   // [E, F]
    const float* bvec   = (const float*)d_in[2];   // [E]
    const float* alphas = (const float*)d_in[3];   // [E]
    float* out = (float*)d_out;                    // [N]

    const int E = in_sizes[2];         // 256
    const int F = in_sizes[1] / E;     // 512
    const int N = in_sizes[0] / F;     // 131072

    (void)E; (void)F;
    prep_kernel<<<(E_DIM * (F_DIM / 4)) / 256, 256>>>(Wm);

    cudaFuncSetAttribute(adaboost_mma_kernel,
                         cudaFuncAttributeMaxDynamicSharedMemorySize, DSMEM_BYTES);
    adaboost_mma_kernel<<<N / BM, 256, DSMEM_BYTES>>>(x, Wm, bvec, alphas, out);
}